// round 1
// baseline (speedup 1.0000x reference)
#include <cuda_runtime.h>

#define BATCH 4096
#define FEAT  512
#define NUMC  10000

// Scratch (no cudaMalloc allowed)
__device__ float g_partials[BATCH];
__device__ int   g_is64;

// ---------------------------------------------------------------------------
// Detect whether the labels buffer is int64 or int32.
// If int64 (values < 10000), every odd 32-bit word of the first 4096 words
// is the zero high-half. If int32, odd words are random labels in [0,10000):
// P(all 2048 are zero) ~ 10^-8192. Deterministic function of the input.
// ---------------------------------------------------------------------------
__global__ void detect_labels_kernel(const int* __restrict__ labels32) {
    __shared__ int bad;
    if (threadIdx.x == 0) bad = 0;
    __syncthreads();
    int local_bad = 0;
    for (int i = threadIdx.x; i < BATCH / 2; i += blockDim.x) {
        if (labels32[2 * i + 1] != 0) local_bad = 1;
    }
    if (local_bad) atomicOr(&bad, 1);
    __syncthreads();
    if (threadIdx.x == 0) g_is64 = bad ? 0 : 1;
}

// ---------------------------------------------------------------------------
// One warp per batch row: d_b = sum_k (x[b,k] - centers[label_b, k])^2
// 512 floats per row = 128 float4; 32 lanes x 4 float4 each. Fully coalesced.
// ---------------------------------------------------------------------------
__global__ void __launch_bounds__(256)
dist_kernel(const float* __restrict__ x,
            const int*   __restrict__ labels32,
            const float* __restrict__ centers) {
    int warp = (blockIdx.x * blockDim.x + threadIdx.x) >> 5;
    int lane = threadIdx.x & 31;
    if (warp >= BATCH) return;

    int lab = g_is64 ? labels32[2 * warp] : labels32[warp];

    const float4* xr = reinterpret_cast<const float4*>(x + (size_t)warp * FEAT);
    const float4* cr = reinterpret_cast<const float4*>(centers + (size_t)lab * FEAT);

    float acc = 0.0f;
#pragma unroll
    for (int i = 0; i < 4; i++) {
        float4 xv = xr[lane + 32 * i];
        float4 cv = cr[lane + 32 * i];
        float d0 = xv.x - cv.x;
        float d1 = xv.y - cv.y;
        float d2 = xv.z - cv.z;
        float d3 = xv.w - cv.w;
        acc = fmaf(d0, d0, acc);
        acc = fmaf(d1, d1, acc);
        acc = fmaf(d2, d2, acc);
        acc = fmaf(d3, d3, acc);
    }
#pragma unroll
    for (int o = 16; o > 0; o >>= 1)
        acc += __shfl_xor_sync(0xffffffffu, acc, o);

    if (lane == 0) {
        // clip(dist, 1e-12, 1e12) on the surviving (diagonal) entry
        acc = fminf(fmaxf(acc, 1e-12f), 1e12f);
        g_partials[warp] = acc;
    }
}

// ---------------------------------------------------------------------------
// Deterministic single-block reduction of the 4096 partials.
// Adds the (C-1)*1e-12 contribution of the clipped masked zeros.
// ---------------------------------------------------------------------------
__global__ void __launch_bounds__(1024)
reduce_kernel(float* __restrict__ out) {
    __shared__ float sh[32];
    int t = threadIdx.x;
    float s = 0.0f;
#pragma unroll
    for (int i = 0; i < BATCH / 1024; i++)
        s += g_partials[t + i * 1024];
#pragma unroll
    for (int o = 16; o > 0; o >>= 1)
        s += __shfl_xor_sync(0xffffffffu, s, o);
    if ((t & 31) == 0) sh[t >> 5] = s;
    __syncthreads();
    if (t < 32) {
        s = sh[t];
#pragma unroll
        for (int o = 16; o > 0; o >>= 1)
            s += __shfl_xor_sync(0xffffffffu, s, o);
        if (t == 0) {
            float base = (float)((double)(NUMC - 1) * 1e-12); // clipped zeros, per row
            out[0] = s / (float)BATCH + base;
        }
    }
}

extern "C" void kernel_launch(void* const* d_in, const int* in_sizes, int n_in,
                              void* d_out, int out_size) {
    const float* x       = (const float*)d_in[0];
    const int*   labels  = (const int*)  d_in[1];
    const float* centers = (const float*)d_in[2];
    float*       out     = (float*)d_out;

    detect_labels_kernel<<<1, 512>>>(labels);
    dist_kernel<<<BATCH / 8, 256>>>(x, labels, centers);  // 512 blocks, 8 warps each
    reduce_kernel<<<1, 1024>>>(out);
}

// round 2
// speedup vs baseline: 1.2403x; 1.2403x over previous
#include <cuda_runtime.h>

#define BATCH 4096
#define FEAT  512
#define NUMC  10000

#define BLOCK_THREADS 256
#define WARPS_PER_BLOCK (BLOCK_THREADS / 32)
#define GRID_BLOCKS (BATCH / WARPS_PER_BLOCK)   // 512

// Scratch (no cudaMalloc allowed)
__device__ float g_partials[BATCH];
__device__ int   g_count;   // zero-initialized; reset to 0 by last block each run

// ---------------------------------------------------------------------------
// Single fused kernel:
//  - per-warp label-dtype detection (int64 vs int32) from a fixed 32-word probe
//  - one warp per batch row: d_b = sum_k (x[b,k] - centers[label_b,k])^2
//  - last-block-done deterministic reduction to the scalar loss
// ---------------------------------------------------------------------------
__global__ void __launch_bounds__(BLOCK_THREADS)
center_loss_kernel(const float* __restrict__ x,
                   const int*   __restrict__ labels32,
                   const float* __restrict__ centers,
                   float*       __restrict__ out) {
    const int lane = threadIdx.x & 31;
    const int warp = (blockIdx.x * BLOCK_THREADS + threadIdx.x) >> 5;  // == row b

    // --- dtype detection: probe the same 32 odd words in every warp ----------
    // int64 labels (< 10000): high halves all zero -> ballot == 0.
    // int32 labels: these are labels[1],[3],...,[63]; P(all zero) = 1e-128.
    // Indices stay within [0, 4096) so no OOB for the int32 case (16 KB buffer).
    int probe = __ldg(&labels32[2 * lane + 1]);
    bool is64 = (__ballot_sync(0xffffffffu, probe != 0) == 0u);

    int lab = is64 ? __ldg(&labels32[2 * warp]) : __ldg(&labels32[warp]);

    // --- squared distance for this row ---------------------------------------
    const float4* xr = reinterpret_cast<const float4*>(x + (size_t)warp * FEAT);
    const float4* cr = reinterpret_cast<const float4*>(centers + (size_t)lab * FEAT);

    float acc = 0.0f;
#pragma unroll
    for (int i = 0; i < 4; i++) {
        float4 xv = __ldg(&xr[lane + 32 * i]);
        float4 cv = __ldg(&cr[lane + 32 * i]);
        float d0 = xv.x - cv.x;
        float d1 = xv.y - cv.y;
        float d2 = xv.z - cv.z;
        float d3 = xv.w - cv.w;
        acc = fmaf(d0, d0, acc);
        acc = fmaf(d1, d1, acc);
        acc = fmaf(d2, d2, acc);
        acc = fmaf(d3, d3, acc);
    }
#pragma unroll
    for (int o = 16; o > 0; o >>= 1)
        acc += __shfl_xor_sync(0xffffffffu, acc, o);

    if (lane == 0) {
        // clip(dist, 1e-12, 1e12) on the surviving (diagonal) entry
        g_partials[warp] = fminf(fmaxf(acc, 1e-12f), 1e12f);
    }

    // --- last-block-done final reduction (deterministic, fixed order) --------
    __shared__ bool is_last;
    __threadfence();
    __syncthreads();
    if (threadIdx.x == 0) {
        int c = atomicAdd(&g_count, 1);
        is_last = (c == GRID_BLOCKS - 1);
    }
    __syncthreads();

    if (is_last) {
        __shared__ float sh[WARPS_PER_BLOCK];
        float s = 0.0f;
#pragma unroll
        for (int i = 0; i < BATCH / BLOCK_THREADS; i++)
            s += g_partials[threadIdx.x + i * BLOCK_THREADS];
#pragma unroll
        for (int o = 16; o > 0; o >>= 1)
            s += __shfl_xor_sync(0xffffffffu, s, o);
        if (lane == 0) sh[threadIdx.x >> 5] = s;
        __syncthreads();
        if (threadIdx.x == 0) {
            float tot = 0.0f;
#pragma unroll
            for (int w = 0; w < WARPS_PER_BLOCK; w++) tot += sh[w];
            float base = (float)((double)(NUMC - 1) * 1e-12); // clipped masked zeros
            out[0] = tot / (float)BATCH + base;
            g_count = 0;  // replay-safe reset
        }
    }
}

extern "C" void kernel_launch(void* const* d_in, const int* in_sizes, int n_in,
                              void* d_out, int out_size) {
    const float* x       = (const float*)d_in[0];
    const int*   labels  = (const int*)  d_in[1];
    const float* centers = (const float*)d_in[2];
    float*       out     = (float*)d_out;

    center_loss_kernel<<<GRID_BLOCKS, BLOCK_THREADS>>>(x, labels, centers, out);
}